// round 1
// baseline (speedup 1.0000x reference)
#include <cuda_runtime.h>

#define N_DATA 200000
#define N_CAND 16
#define NN 200016           // N_DATA + N_CAND
#define F_IN 128
#define NE 6400000

// ---------------- device scratch (no allocations allowed) ----------------
__device__ float g_h0  [NN * 16];   // layer1 pre-agg (x @ W1), later h1
__device__ float g_agg1[NN * 16];
__device__ float g_h0b [NN * 16];   // layer2 pre-agg (h1 @ W2)
__device__ float g_agg2[NN * 16];
__device__ float g_nf  [NN * 16];   // node_feat (post conv2 relu)
__device__ float g_deg [NN];
__device__ float g_dinv[NN];
__device__ unsigned long long g_slot[2];   // packed argmax slots

// orderable float bits (monotone map float -> uint)
__device__ __forceinline__ unsigned ford(float v) {
    unsigned u = __float_as_uint(v);
    return (u & 0x80000000u) ? ~u : (u | 0x80000000u);
}

// ---------------- kernels ----------------

__global__ void k_init() {
    int i = blockIdx.x * blockDim.x + threadIdx.x;
    int stride = gridDim.x * blockDim.x;
    for (int t = i; t < NN * 16; t += stride) { g_agg1[t] = 0.f; g_agg2[t] = 0.f; }
    for (int t = i; t < NN; t += stride) g_deg[t] = 1.0f;   // self-loop
    if (i == 0) { g_slot[0] = 0ull; g_slot[1] = 0ull; }
}

__global__ void k_deg(const int* __restrict__ ei) {
    int e = blockIdx.x * blockDim.x + threadIdx.x;
    if (e < NE) atomicAdd(&g_deg[ei[NE + e]], 1.0f);
}

__global__ void k_dinv() {
    int i = blockIdx.x * blockDim.x + threadIdx.x;
    if (i < NN) g_dinv[i] = rsqrtf(g_deg[i]);
}

// h0 = concat(x, candidates) @ W1   (128 -> 16), 8 rows per 128-thread block
__global__ __launch_bounds__(128) void k_gemm1(const float* __restrict__ x,
                                               const float* __restrict__ cand,
                                               const float* __restrict__ W) {
    __shared__ float Ws[128 * 16];
    __shared__ float Xs[8][128];
    int tid = threadIdx.x;
    #pragma unroll
    for (int t = tid; t < 2048; t += 128) Ws[t] = W[t];
    int row0 = blockIdx.x * 8;
    #pragma unroll
    for (int r = 0; r < 8; r++) {
        int row = row0 + r;
        if (row < NN) {
            const float* src = (row < N_DATA) ? (x + (size_t)row * F_IN)
                                              : (cand + (size_t)(row - N_DATA) * F_IN);
            Xs[r][tid] = src[tid];
        }
    }
    __syncthreads();
    int r = tid >> 4, j = tid & 15;
    int row = row0 + r;
    if (row < NN) {
        float acc = 0.f;
        #pragma unroll
        for (int k = 0; k < 128; k++) acc += Xs[r][k] * Ws[k * 16 + j];
        g_h0[row * 16 + j] = acc;
    }
}

// edge scatter: agg[dst] += h[src] * dinv[src]*dinv[dst]; 4 threads/edge, float4 each
template <int PHASE>
__global__ __launch_bounds__(256) void k_scatter(const int* __restrict__ ei) {
    long long tid = (long long)blockIdx.x * blockDim.x + threadIdx.x;
    if (tid >= (long long)NE * 4) return;
    int e = (int)(tid >> 2), q = (int)(tid & 3);
    int s = __ldg(ei + e);
    int d = __ldg(ei + NE + e);
    float c = g_dinv[s] * g_dinv[d];
    const float* h  = (PHASE == 0) ? g_h0  : g_h0b;
    float*       ag = (PHASE == 0) ? g_agg1 : g_agg2;
    float4 v = *(const float4*)(h + (size_t)s * 16 + q * 4);
    float* o = ag + (size_t)d * 16 + q * 4;
    atomicAdd(o + 0, v.x * c);
    atomicAdd(o + 1, v.y * c);
    atomicAdd(o + 2, v.z * c);
    atomicAdd(o + 3, v.w * c);
}

// h1 = relu(agg1 + h0*dinv^2 + cb1);  h0b = h1 @ W2  (fused)
__global__ __launch_bounds__(128) void k_fin1g2(const float* __restrict__ cb1,
                                                const float* __restrict__ W2) {
    __shared__ float Ws[256];
    __shared__ float H[8][16];
    int tid = threadIdx.x;
    Ws[tid] = W2[tid];
    Ws[tid + 128] = W2[tid + 128];
    int r = tid >> 4, j = tid & 15;
    int row = blockIdx.x * 8 + r;
    if (row < NN) {
        float di = g_dinv[row];
        float v = g_agg1[row * 16 + j] + g_h0[row * 16 + j] * di * di + cb1[j];
        H[r][j] = fmaxf(v, 0.f);
    }
    __syncthreads();
    if (row < NN) {
        float acc = 0.f;
        #pragma unroll
        for (int k = 0; k < 16; k++) acc += H[r][k] * Ws[k * 16 + j];
        g_h0b[row * 16 + j] = acc;
    }
}

// node_feat = relu(agg2 + h0b*dinv^2 + cb2); out1 = mlp1(node_feat); argmax over rows<N_DATA
__global__ __launch_bounds__(128) void k_fin2mlp1(const float* __restrict__ cb2,
                                                  const float* __restrict__ m1w1,
                                                  const float* __restrict__ m1b1,
                                                  const float* __restrict__ m1w2,
                                                  const float* __restrict__ m1b2,
                                                  float* __restrict__ out1) {
    __shared__ float W1s[256], b1s[16], w2s[16];
    __shared__ float NF[8][16], S[8][16];
    __shared__ unsigned long long best[8];
    int tid = threadIdx.x;
    W1s[tid] = m1w1[tid];
    W1s[tid + 128] = m1w1[tid + 128];
    if (tid < 16) { b1s[tid] = m1b1[tid]; w2s[tid] = m1w2[tid]; }
    int r = tid >> 4, j = tid & 15;
    int row = blockIdx.x * 8 + r;
    if (row < NN) {
        float di = g_dinv[row];
        float v = g_agg2[row * 16 + j] + g_h0b[row * 16 + j] * di * di + cb2[j];
        v = fmaxf(v, 0.f);
        NF[r][j] = v;
        g_nf[row * 16 + j] = v;
    }
    __syncthreads();
    if (row < NN) {
        float acc = b1s[j];
        #pragma unroll
        for (int k = 0; k < 16; k++) acc += NF[r][k] * W1s[k * 16 + j];
        S[r][j] = fmaxf(acc, 0.f);
    }
    __syncthreads();
    if (j == 0) {
        unsigned long long key = 0ull;
        if (row < NN) {
            float o = m1b2[0];
            #pragma unroll
            for (int k = 0; k < 16; k++) o += S[r][k] * w2s[k];
            out1[row] = o;
            if (row < N_DATA)
                key = ((unsigned long long)ford(o) << 32) | (0xFFFFFFFFu - (unsigned)row);
        }
        best[r] = key;
    }
    __syncthreads();
    if (tid == 0) {
        unsigned long long m = best[0];
        #pragma unroll
        for (int r2 = 1; r2 < 8; r2++) m = max(m, best[r2]);
        if (m) atomicMax(&g_slot[0], m);
    }
}

// out2 = mlp2(concat(nf, nf[start])); argmax excluding start
__global__ __launch_bounds__(256) void k_mlp2(const float* __restrict__ m2w1,
                                              const float* __restrict__ m2b1,
                                              const float* __restrict__ m2w2,
                                              const float* __restrict__ m2b2,
                                              float* __restrict__ out2) {
    __shared__ float W1s[32 * 24], tbase[24], w2s[24], sf[16];
    __shared__ unsigned long long wmax[8];
    int tid = threadIdx.x;
    for (int t = tid; t < 768; t += 256) W1s[t] = m2w1[t];
    if (tid < 24) w2s[tid] = m2w2[tid];
    int start = (int)(0xFFFFFFFFu - (unsigned)(g_slot[0] & 0xFFFFFFFFull));
    if (tid < 16) sf[tid] = g_nf[(size_t)start * 16 + tid];
    __syncthreads();
    // per-block precompute of the (constant) starting-feature contribution
    if (tid < 24) {
        float tb = m2b1[tid];
        #pragma unroll
        for (int k = 0; k < 16; k++) tb += sf[k] * W1s[(16 + k) * 24 + tid];
        tbase[tid] = tb;
    }
    __syncthreads();

    int row = blockIdx.x * 256 + tid;
    unsigned long long key = 0ull;
    if (row < NN) {
        float nf[16];
        const float4* p = (const float4*)(g_nf + (size_t)row * 16);
        float4 a = p[0], b = p[1], c = p[2], d = p[3];
        nf[0]=a.x; nf[1]=a.y; nf[2]=a.z; nf[3]=a.w;
        nf[4]=b.x; nf[5]=b.y; nf[6]=b.z; nf[7]=b.w;
        nf[8]=c.x; nf[9]=c.y; nf[10]=c.z; nf[11]=c.w;
        nf[12]=d.x; nf[13]=d.y; nf[14]=d.z; nf[15]=d.w;
        float o = m2b2[0];
        #pragma unroll
        for (int j = 0; j < 24; j++) {
            float tj = tbase[j];
            #pragma unroll
            for (int k = 0; k < 16; k++) tj += nf[k] * W1s[k * 24 + j];
            o += fmaxf(tj, 0.f) * w2s[j];
        }
        out2[row] = o;
        if (row != start)
            key = ((unsigned long long)ford(o) << 32) | (0xFFFFFFFFu - (unsigned)row);
    }
    #pragma unroll
    for (int off = 16; off; off >>= 1)
        key = max(key, __shfl_xor_sync(0xffffffffu, key, off));
    if ((tid & 31) == 0) wmax[tid >> 5] = key;
    __syncthreads();
    if (tid == 0) {
        unsigned long long m = wmax[0];
        #pragma unroll
        for (int w = 1; w < 8; w++) m = max(m, wmax[w]);
        if (m) atomicMax(&g_slot[1], m);
    }
}

// write scalars + new_features
__global__ void k_final(const float* __restrict__ x, const float* __restrict__ cand,
                        float* __restrict__ dout) {
    int start = (int)(0xFFFFFFFFu - (unsigned)(g_slot[0] & 0xFFFFFFFFull));
    int end   = (int)(0xFFFFFFFFu - (unsigned)(g_slot[1] & 0xFFFFFFFFull));
    if (threadIdx.x == 0) {
        dout[0] = (float)start;
        dout[1] = (float)end;
        dout[2] = (end >= N_DATA) ? 1.0f : 0.0f;
    }
    const float* src = (end < N_DATA) ? (x + (size_t)end * F_IN)
                                      : (cand + (size_t)(end - N_DATA) * F_IN);
    if (threadIdx.x < F_IN) dout[3 + threadIdx.x] = src[threadIdx.x];
}

// ---------------- launch ----------------
extern "C" void kernel_launch(void* const* d_in, const int* in_sizes, int n_in,
                              void* d_out, int out_size) {
    const float* x    = (const float*)d_in[0];
    const float* cand = (const float*)d_in[1];
    const int*   ei   = (const int*)d_in[2];
    const float* cw1  = (const float*)d_in[3];
    const float* cb1  = (const float*)d_in[4];
    const float* cw2  = (const float*)d_in[5];
    const float* cb2  = (const float*)d_in[6];
    const float* m1w1 = (const float*)d_in[7];
    const float* m1b1 = (const float*)d_in[8];
    const float* m1w2 = (const float*)d_in[9];
    const float* m1b2 = (const float*)d_in[10];
    const float* m2w1 = (const float*)d_in[11];
    const float* m2b1 = (const float*)d_in[12];
    const float* m2w2 = (const float*)d_in[13];
    const float* m2b2 = (const float*)d_in[14];
    float* out = (float*)d_out;

    k_init<<<2048, 256>>>();
    k_deg<<<NE / 256, 256>>>(ei);
    k_dinv<<<(NN + 255) / 256, 256>>>();
    k_gemm1<<<(NN + 7) / 8, 128>>>(x, cand, cw1);
    k_scatter<0><<<(int)(((long long)NE * 4) / 256), 256>>>(ei);
    k_fin1g2<<<(NN + 7) / 8, 128>>>(cb1, cw2);
    k_scatter<1><<<(int)(((long long)NE * 4) / 256), 256>>>(ei);
    k_fin2mlp1<<<(NN + 7) / 8, 128>>>(cb2, m1w1, m1b1, m1w2, m1b2, out + 131);
    k_mlp2<<<(NN + 255) / 256, 256>>>(m2w1, m2b1, m2w2, m2b2, out + 131 + NN);
    k_final<<<1, 128>>>(x, cand, out);
}

// round 2
// speedup vs baseline: 1.3486x; 1.3486x over previous
#include <cuda_runtime.h>

#define N_DATA 200000
#define N_CAND 16
#define NN 200016           // N_DATA + N_CAND
#define F_IN 128
#define NE 6400000

// ---------------- device scratch (no allocations allowed) ----------------
__device__ float g_h0  [NN * 16];   // layer1 pre-agg (x @ W1)
__device__ float g_agg1[NN * 16];
__device__ float g_h0b [NN * 16];   // layer2 pre-agg (h1 @ W2)
__device__ float g_agg2[NN * 16];
__device__ float g_nf  [NN * 16];   // node_feat (post conv2 relu)
__device__ float g_deg [NN];
__device__ float g_dinv[NN];
__device__ float g_coef[NE];        // per-edge dinv[s]*dinv[d]
__device__ unsigned long long g_slot[2];   // packed argmax slots

// orderable float bits (monotone map float -> uint)
__device__ __forceinline__ unsigned ford(float v) {
    unsigned u = __float_as_uint(v);
    return (u & 0x80000000u) ? ~u : (u | 0x80000000u);
}

// ---------------- kernels ----------------

__global__ void k_init() {
    int i = blockIdx.x * blockDim.x + threadIdx.x;
    int stride = gridDim.x * blockDim.x;
    for (int t = i; t < NN * 16; t += stride) { g_agg1[t] = 0.f; g_agg2[t] = 0.f; }
    for (int t = i; t < NN; t += stride) g_deg[t] = 1.0f;   // self-loop
    if (i == 0) { g_slot[0] = 0ull; g_slot[1] = 0ull; }
}

__global__ void k_deg(const int* __restrict__ ei) {
    int e = blockIdx.x * blockDim.x + threadIdx.x;
    if (e < NE) atomicAdd(&g_deg[ei[NE + e]], 1.0f);
}

__global__ void k_dinv() {
    int i = blockIdx.x * blockDim.x + threadIdx.x;
    if (i < NN) g_dinv[i] = rsqrtf(g_deg[i]);
}

__global__ void k_coef(const int* __restrict__ ei) {
    int e = blockIdx.x * blockDim.x + threadIdx.x;
    if (e < NE) g_coef[e] = g_dinv[__ldg(ei + e)] * g_dinv[__ldg(ei + NE + e)];
}

// h0 = concat(x, candidates) @ W1 (128 -> 16). 16 rows per 256-thread block.
// Both shared tiles padded to stride 132 -> conflict-free LDS.128 on each side.
__global__ __launch_bounds__(256) void k_gemm1(const float* __restrict__ x,
                                               const float* __restrict__ cand,
                                               const float* __restrict__ W) {
    __shared__ float Wt[16][132];   // W transposed: Wt[j][k]
    __shared__ float Xs[16][132];
    int tid = threadIdx.x;
    for (int t = tid; t < 2048; t += 256) {
        int k = t >> 4, j = t & 15;
        Wt[j][k] = W[t];
    }
    int row0 = blockIdx.x * 16;
    #pragma unroll
    for (int t = tid; t < 16 * 128; t += 256) {
        int r = t >> 7, c = t & 127;
        int row = row0 + r;
        if (row < NN) {
            const float* src = (row < N_DATA) ? (x + (size_t)row * F_IN)
                                              : (cand + (size_t)(row - N_DATA) * F_IN);
            Xs[r][c] = src[c];
        }
    }
    __syncthreads();
    int half = tid >> 7;              // 0/1 -> rows 0-7 vs 8-15
    int lt   = tid & 127;
    int r    = (lt & 7) + half * 8;   // warp covers r=0..7, conflict-free on Xs
    int j    = lt >> 3;               // 4 distinct j per warp, broadcast on Wt
    int row  = row0 + r;
    if (row < NN) {
        float acc = 0.f;
        #pragma unroll
        for (int k = 0; k < 128; k += 4) {
            float4 xv = *(const float4*)&Xs[r][k];
            float4 wv = *(const float4*)&Wt[j][k];
            acc += xv.x * wv.x + xv.y * wv.y + xv.z * wv.z + xv.w * wv.w;
        }
        g_h0[row * 16 + j] = acc;
    }
}

// edge scatter: agg[dst] += h[src] * coef[e]; 4 threads/edge, one red.v4 each
template <int PHASE>
__global__ __launch_bounds__(256) void k_scatter(const int* __restrict__ ei) {
    long long tid = (long long)blockIdx.x * blockDim.x + threadIdx.x;
    if (tid >= (long long)NE * 4) return;
    int e = (int)(tid >> 2), q = (int)(tid & 3);
    int s = __ldg(ei + e);
    int d = __ldg(ei + NE + e);
    float c = g_coef[e];
    const float* h  = (PHASE == 0) ? g_h0  : g_h0b;
    float*       ag = (PHASE == 0) ? g_agg1 : g_agg2;
    float4 v = *(const float4*)(h + (size_t)s * 16 + q * 4);
    float* o = ag + (size_t)d * 16 + q * 4;
    asm volatile("red.global.add.v4.f32 [%0], {%1, %2, %3, %4};"
                 :: "l"(o), "f"(v.x * c), "f"(v.y * c), "f"(v.z * c), "f"(v.w * c)
                 : "memory");
}

// h1 = relu(agg1 + h0*dinv^2 + cb1);  h0b = h1 @ W2  (fused)
__global__ __launch_bounds__(128) void k_fin1g2(const float* __restrict__ cb1,
                                                const float* __restrict__ W2) {
    __shared__ float Ws[256];
    __shared__ float H[8][16];
    int tid = threadIdx.x;
    Ws[tid] = W2[tid];
    Ws[tid + 128] = W2[tid + 128];
    int r = tid >> 4, j = tid & 15;
    int row = blockIdx.x * 8 + r;
    if (row < NN) {
        float di = g_dinv[row];
        float v = g_agg1[row * 16 + j] + g_h0[row * 16 + j] * di * di + cb1[j];
        H[r][j] = fmaxf(v, 0.f);
    }
    __syncthreads();
    if (row < NN) {
        float acc = 0.f;
        #pragma unroll
        for (int k = 0; k < 16; k++) acc += H[r][k] * Ws[k * 16 + j];
        g_h0b[row * 16 + j] = acc;
    }
}

// node_feat = relu(agg2 + h0b*dinv^2 + cb2); out1 = mlp1(node_feat); argmax rows<N_DATA
__global__ __launch_bounds__(128) void k_fin2mlp1(const float* __restrict__ cb2,
                                                  const float* __restrict__ m1w1,
                                                  const float* __restrict__ m1b1,
                                                  const float* __restrict__ m1w2,
                                                  const float* __restrict__ m1b2,
                                                  float* __restrict__ out1) {
    __shared__ float W1s[256], b1s[16], w2s[16];
    __shared__ float NF[8][16], S[8][16];
    __shared__ unsigned long long best[8];
    int tid = threadIdx.x;
    W1s[tid] = m1w1[tid];
    W1s[tid + 128] = m1w1[tid + 128];
    if (tid < 16) { b1s[tid] = m1b1[tid]; w2s[tid] = m1w2[tid]; }
    int r = tid >> 4, j = tid & 15;
    int row = blockIdx.x * 8 + r;
    if (row < NN) {
        float di = g_dinv[row];
        float v = g_agg2[row * 16 + j] + g_h0b[row * 16 + j] * di * di + cb2[j];
        v = fmaxf(v, 0.f);
        NF[r][j] = v;
        g_nf[row * 16 + j] = v;
    }
    __syncthreads();
    if (row < NN) {
        float acc = b1s[j];
        #pragma unroll
        for (int k = 0; k < 16; k++) acc += NF[r][k] * W1s[k * 16 + j];
        S[r][j] = fmaxf(acc, 0.f);
    }
    __syncthreads();
    if (j == 0) {
        unsigned long long key = 0ull;
        if (row < NN) {
            float o = m1b2[0];
            #pragma unroll
            for (int k = 0; k < 16; k++) o += S[r][k] * w2s[k];
            out1[row] = o;
            if (row < N_DATA)
                key = ((unsigned long long)ford(o) << 32) | (0xFFFFFFFFu - (unsigned)row);
        }
        best[r] = key;
    }
    __syncthreads();
    if (tid == 0) {
        unsigned long long m = best[0];
        #pragma unroll
        for (int r2 = 1; r2 < 8; r2++) m = max(m, best[r2]);
        if (m) atomicMax(&g_slot[0], m);
    }
}

// out2 = mlp2(concat(nf, nf[start])); argmax excluding start
__global__ __launch_bounds__(256) void k_mlp2(const float* __restrict__ m2w1,
                                              const float* __restrict__ m2b1,
                                              const float* __restrict__ m2w2,
                                              const float* __restrict__ m2b2,
                                              float* __restrict__ out2) {
    __shared__ float W1s[32 * 24], tbase[24], w2s[24], sf[16];
    __shared__ unsigned long long wmax[8];
    int tid = threadIdx.x;
    for (int t = tid; t < 768; t += 256) W1s[t] = m2w1[t];
    if (tid < 24) w2s[tid] = m2w2[tid];
    int start = (int)(0xFFFFFFFFu - (unsigned)(g_slot[0] & 0xFFFFFFFFull));
    if (tid < 16) sf[tid] = g_nf[(size_t)start * 16 + tid];
    __syncthreads();
    if (tid < 24) {
        float tb = m2b1[tid];
        #pragma unroll
        for (int k = 0; k < 16; k++) tb += sf[k] * W1s[(16 + k) * 24 + tid];
        tbase[tid] = tb;
    }
    __syncthreads();

    int row = blockIdx.x * 256 + tid;
    unsigned long long key = 0ull;
    if (row < NN) {
        float nf[16];
        const float4* p = (const float4*)(g_nf + (size_t)row * 16);
        float4 a = p[0], b = p[1], c = p[2], d = p[3];
        nf[0]=a.x; nf[1]=a.y; nf[2]=a.z; nf[3]=a.w;
        nf[4]=b.x; nf[5]=b.y; nf[6]=b.z; nf[7]=b.w;
        nf[8]=c.x; nf[9]=c.y; nf[10]=c.z; nf[11]=c.w;
        nf[12]=d.x; nf[13]=d.y; nf[14]=d.z; nf[15]=d.w;
        float o = m2b2[0];
        #pragma unroll
        for (int j = 0; j < 24; j++) {
            float tj = tbase[j];
            #pragma unroll
            for (int k = 0; k < 16; k++) tj += nf[k] * W1s[k * 24 + j];
            o += fmaxf(tj, 0.f) * w2s[j];
        }
        out2[row] = o;
        if (row != start)
            key = ((unsigned long long)ford(o) << 32) | (0xFFFFFFFFu - (unsigned)row);
    }
    #pragma unroll
    for (int off = 16; off; off >>= 1)
        key = max(key, __shfl_xor_sync(0xffffffffu, key, off));
    if ((tid & 31) == 0) wmax[tid >> 5] = key;
    __syncthreads();
    if (tid == 0) {
        unsigned long long m = wmax[0];
        #pragma unroll
        for (int w = 1; w < 8; w++) m = max(m, wmax[w]);
        if (m) atomicMax(&g_slot[1], m);
    }
}

// write scalars + new_features
__global__ void k_final(const float* __restrict__ x, const float* __restrict__ cand,
                        float* __restrict__ dout) {
    int start = (int)(0xFFFFFFFFu - (unsigned)(g_slot[0] & 0xFFFFFFFFull));
    int end   = (int)(0xFFFFFFFFu - (unsigned)(g_slot[1] & 0xFFFFFFFFull));
    if (threadIdx.x == 0) {
        dout[0] = (float)start;
        dout[1] = (float)end;
        dout[2] = (end >= N_DATA) ? 1.0f : 0.0f;
    }
    const float* src = (end < N_DATA) ? (x + (size_t)end * F_IN)
                                      : (cand + (size_t)(end - N_DATA) * F_IN);
    if (threadIdx.x < F_IN) dout[3 + threadIdx.x] = src[threadIdx.x];
}

// ---------------- launch ----------------
extern "C" void kernel_launch(void* const* d_in, const int* in_sizes, int n_in,
                              void* d_out, int out_size) {
    const float* x    = (const float*)d_in[0];
    const float* cand = (const float*)d_in[1];
    const int*   ei   = (const int*)d_in[2];
    const float* cw1  = (const float*)d_in[3];
    const float* cb1  = (const float*)d_in[4];
    const float* cw2  = (const float*)d_in[5];
    const float* cb2  = (const float*)d_in[6];
    const float* m1w1 = (const float*)d_in[7];
    const float* m1b1 = (const float*)d_in[8];
    const float* m1w2 = (const float*)d_in[9];
    const float* m1b2 = (const float*)d_in[10];
    const float* m2w1 = (const float*)d_in[11];
    const float* m2b1 = (const float*)d_in[12];
    const float* m2w2 = (const float*)d_in[13];
    const float* m2b2 = (const float*)d_in[14];
    float* out = (float*)d_out;

    k_init<<<2048, 256>>>();
    k_deg<<<NE / 256, 256>>>(ei);
    k_dinv<<<(NN + 255) / 256, 256>>>();
    k_coef<<<NE / 256, 256>>>(ei);
    k_gemm1<<<(NN + 15) / 16, 256>>>(x, cand, cw1);
    k_scatter<0><<<(int)(((long long)NE * 4) / 256), 256>>>(ei);
    k_fin1g2<<<(NN + 7) / 8, 128>>>(cb1, cw2);
    k_scatter<1><<<(int)(((long long)NE * 4) / 256), 256>>>(ei);
    k_fin2mlp1<<<(NN + 7) / 8, 128>>>(cb2, m1w1, m1b1, m1w2, m1b2, out + 131);
    k_mlp2<<<(NN + 255) / 256, 256>>>(m2w1, m2b1, m2w2, m2b2, out + 131 + NN);
    k_final<<<1, 128>>>(x, cand, out);
}

// round 3
// speedup vs baseline: 1.5891x; 1.1783x over previous
#include <cuda_runtime.h>

#define N_DATA 200000
#define N_CAND 16
#define NN 200016           // N_DATA + N_CAND
#define F_IN 128
#define NE 6400000

// ---------------- device scratch (no allocations allowed) ----------------
__device__ float g_h0s [NN * 16];   // layer1 pre-agg, pre-scaled by dinv: (x@W1)*dinv
__device__ float g_agg1[NN * 16];
__device__ float g_h2s [NN * 16];   // layer2 pre-agg, pre-scaled: (h1@W2)*dinv
__device__ float g_agg2[NN * 16];
__device__ float g_nf  [NN * 16];   // node_feat (post conv2 relu)
__device__ float g_deg [NN];
__device__ float g_dinv[NN];
__device__ unsigned long long g_slot[2];   // packed argmax slots

// orderable float bits (monotone map float -> uint)
__device__ __forceinline__ unsigned ford(float v) {
    unsigned u = __float_as_uint(v);
    return (u & 0x80000000u) ? ~u : (u | 0x80000000u);
}

// ---------------- kernels ----------------

__global__ void k_init() {
    int i = blockIdx.x * blockDim.x + threadIdx.x;
    int stride = gridDim.x * blockDim.x;
    for (int t = i; t < NN * 16; t += stride) { g_agg1[t] = 0.f; g_agg2[t] = 0.f; }
    for (int t = i; t < NN; t += stride) g_deg[t] = 1.0f;   // self-loop
    if (i == 0) { g_slot[0] = 0ull; g_slot[1] = 0ull; }
}

__global__ void k_deg(const int* __restrict__ ei) {
    int e = blockIdx.x * blockDim.x + threadIdx.x;
    if (e < NE) {
        float* a = &g_deg[__ldg(ei + NE + e)];
        asm volatile("red.global.add.f32 [%0], %1;" :: "l"(a), "f"(1.0f) : "memory");
    }
}

// h0s = (concat(x, candidates) @ W1) * dinv. Also stores g_dinv.
// 16 rows per 256-thread block; padded shared tiles -> conflict-free LDS.128.
__global__ __launch_bounds__(256) void k_gemm1(const float* __restrict__ x,
                                               const float* __restrict__ cand,
                                               const float* __restrict__ W) {
    __shared__ float Wt[16][132];   // W transposed: Wt[j][k]
    __shared__ float Xs[16][132];
    int tid = threadIdx.x;
    for (int t = tid; t < 2048; t += 256) {
        int k = t >> 4, j = t & 15;
        Wt[j][k] = W[t];
    }
    int row0 = blockIdx.x * 16;
    #pragma unroll
    for (int t = tid; t < 16 * 128; t += 256) {
        int r = t >> 7, c = t & 127;
        int row = row0 + r;
        if (row < NN) {
            const float* src = (row < N_DATA) ? (x + (size_t)row * F_IN)
                                              : (cand + (size_t)(row - N_DATA) * F_IN);
            Xs[r][c] = src[c];
        }
    }
    // one thread per row computes+stores dinv
    if (tid < 16) {
        int row = row0 + tid;
        if (row < NN) g_dinv[row] = rsqrtf(g_deg[row]);
    }
    __syncthreads();
    int half = tid >> 7;
    int lt   = tid & 127;
    int r    = (lt & 7) + half * 8;
    int j    = lt >> 3;
    int row  = row0 + r;
    if (row < NN) {
        float acc = 0.f;
        #pragma unroll
        for (int k = 0; k < 128; k += 4) {
            float4 xv = *(const float4*)&Xs[r][k];
            float4 wv = *(const float4*)&Wt[j][k];
            acc += xv.x * wv.x + xv.y * wv.y + xv.z * wv.z + xv.w * wv.w;
        }
        g_h0s[row * 16 + j] = acc * g_dinv[row];
    }
}

// edge scatter: agg[dst] += hs[src]; 4 threads/edge, one red.v4 each. No coef.
template <int PHASE>
__global__ __launch_bounds__(256) void k_scatter(const int* __restrict__ ei) {
    long long tid = (long long)blockIdx.x * blockDim.x + threadIdx.x;
    if (tid >= (long long)NE * 4) return;
    int e = (int)(tid >> 2), q = (int)(tid & 3);
    int s = __ldg(ei + e);
    int d = __ldg(ei + NE + e);
    const float* h  = (PHASE == 0) ? g_h0s : g_h2s;
    float*       ag = (PHASE == 0) ? g_agg1 : g_agg2;
    float4 v = *(const float4*)(h + (size_t)s * 16 + q * 4);
    float* o = ag + (size_t)d * 16 + q * 4;
    asm volatile("red.global.add.v4.f32 [%0], {%1, %2, %3, %4};"
                 :: "l"(o), "f"(v.x), "f"(v.y), "f"(v.z), "f"(v.w)
                 : "memory");
}

// h1 = relu((agg1 + h0s)*dinv + cb1);  h2s = (h1 @ W2)*dinv  (fused)
__global__ __launch_bounds__(128) void k_fin1g2(const float* __restrict__ cb1,
                                                const float* __restrict__ W2) {
    __shared__ float Ws[256];
    __shared__ float H[8][16];
    int tid = threadIdx.x;
    Ws[tid] = W2[tid];
    Ws[tid + 128] = W2[tid + 128];
    int r = tid >> 4, j = tid & 15;
    int row = blockIdx.x * 8 + r;
    float di = 0.f;
    if (row < NN) {
        di = g_dinv[row];
        float v = (g_agg1[row * 16 + j] + g_h0s[row * 16 + j]) * di + cb1[j];
        H[r][j] = fmaxf(v, 0.f);
    }
    __syncthreads();
    if (row < NN) {
        float acc = 0.f;
        #pragma unroll
        for (int k = 0; k < 16; k++) acc += H[r][k] * Ws[k * 16 + j];
        g_h2s[row * 16 + j] = acc * di;
    }
}

// nf = relu((agg2 + h2s)*dinv + cb2); out1 = mlp1(nf); argmax rows<N_DATA
__global__ __launch_bounds__(128) void k_fin2mlp1(const float* __restrict__ cb2,
                                                  const float* __restrict__ m1w1,
                                                  const float* __restrict__ m1b1,
                                                  const float* __restrict__ m1w2,
                                                  const float* __restrict__ m1b2,
                                                  float* __restrict__ out1) {
    __shared__ float W1s[256], b1s[16], w2s[16];
    __shared__ float NF[8][16], S[8][16];
    __shared__ unsigned long long best[8];
    int tid = threadIdx.x;
    W1s[tid] = m1w1[tid];
    W1s[tid + 128] = m1w1[tid + 128];
    if (tid < 16) { b1s[tid] = m1b1[tid]; w2s[tid] = m1w2[tid]; }
    int r = tid >> 4, j = tid & 15;
    int row = blockIdx.x * 8 + r;
    if (row < NN) {
        float di = g_dinv[row];
        float v = (g_agg2[row * 16 + j] + g_h2s[row * 16 + j]) * di + cb2[j];
        v = fmaxf(v, 0.f);
        NF[r][j] = v;
        g_nf[row * 16 + j] = v;
    }
    __syncthreads();
    if (row < NN) {
        float acc = b1s[j];
        #pragma unroll
        for (int k = 0; k < 16; k++) acc += NF[r][k] * W1s[k * 16 + j];
        S[r][j] = fmaxf(acc, 0.f);
    }
    __syncthreads();
    if (j == 0) {
        unsigned long long key = 0ull;
        if (row < NN) {
            float o = m1b2[0];
            #pragma unroll
            for (int k = 0; k < 16; k++) o += S[r][k] * w2s[k];
            out1[row] = o;
            if (row < N_DATA)
                key = ((unsigned long long)ford(o) << 32) | (0xFFFFFFFFu - (unsigned)row);
        }
        best[r] = key;
    }
    __syncthreads();
    if (tid == 0) {
        unsigned long long m = best[0];
        #pragma unroll
        for (int r2 = 1; r2 < 8; r2++) m = max(m, best[r2]);
        if (m) atomicMax(&g_slot[0], m);
    }
}

// out2 = mlp2(concat(nf, nf[start])); argmax excluding start
__global__ __launch_bounds__(256) void k_mlp2(const float* __restrict__ m2w1,
                                              const float* __restrict__ m2b1,
                                              const float* __restrict__ m2w2,
                                              const float* __restrict__ m2b2,
                                              float* __restrict__ out2) {
    __shared__ float W1s[32 * 24], tbase[24], w2s[24], sf[16];
    __shared__ unsigned long long wmax[8];
    int tid = threadIdx.x;
    for (int t = tid; t < 768; t += 256) W1s[t] = m2w1[t];
    if (tid < 24) w2s[tid] = m2w2[tid];
    int start = (int)(0xFFFFFFFFu - (unsigned)(g_slot[0] & 0xFFFFFFFFull));
    if (tid < 16) sf[tid] = g_nf[(size_t)start * 16 + tid];
    __syncthreads();
    if (tid < 24) {
        float tb = m2b1[tid];
        #pragma unroll
        for (int k = 0; k < 16; k++) tb += sf[k] * W1s[(16 + k) * 24 + tid];
        tbase[tid] = tb;
    }
    __syncthreads();

    int row = blockIdx.x * 256 + tid;
    unsigned long long key = 0ull;
    if (row < NN) {
        float nf[16];
        const float4* p = (const float4*)(g_nf + (size_t)row * 16);
        float4 a = p[0], b = p[1], c = p[2], d = p[3];
        nf[0]=a.x; nf[1]=a.y; nf[2]=a.z; nf[3]=a.w;
        nf[4]=b.x; nf[5]=b.y; nf[6]=b.z; nf[7]=b.w;
        nf[8]=c.x; nf[9]=c.y; nf[10]=c.z; nf[11]=c.w;
        nf[12]=d.x; nf[13]=d.y; nf[14]=d.z; nf[15]=d.w;
        float o = m2b2[0];
        #pragma unroll
        for (int j = 0; j < 24; j++) {
            float tj = tbase[j];
            #pragma unroll
            for (int k = 0; k < 16; k++) tj += nf[k] * W1s[k * 24 + j];
            o += fmaxf(tj, 0.f) * w2s[j];
        }
        out2[row] = o;
        if (row != start)
            key = ((unsigned long long)ford(o) << 32) | (0xFFFFFFFFu - (unsigned)row);
    }
    #pragma unroll
    for (int off = 16; off; off >>= 1)
        key = max(key, __shfl_xor_sync(0xffffffffu, key, off));
    if ((tid & 31) == 0) wmax[tid >> 5] = key;
    __syncthreads();
    if (tid == 0) {
        unsigned long long m = wmax[0];
        #pragma unroll
        for (int w = 1; w < 8; w++) m = max(m, wmax[w]);
        if (m) atomicMax(&g_slot[1], m);
    }
}

// write scalars + new_features
__global__ void k_final(const float* __restrict__ x, const float* __restrict__ cand,
                        float* __restrict__ dout) {
    int start = (int)(0xFFFFFFFFu - (unsigned)(g_slot[0] & 0xFFFFFFFFull));
    int end   = (int)(0xFFFFFFFFu - (unsigned)(g_slot[1] & 0xFFFFFFFFull));
    if (threadIdx.x == 0) {
        dout[0] = (float)start;
        dout[1] = (float)end;
        dout[2] = (end >= N_DATA) ? 1.0f : 0.0f;
    }
    const float* src = (end < N_DATA) ? (x + (size_t)end * F_IN)
                                      : (cand + (size_t)(end - N_DATA) * F_IN);
    if (threadIdx.x < F_IN) dout[3 + threadIdx.x] = src[threadIdx.x];
}

// ---------------- launch ----------------
extern "C" void kernel_launch(void* const* d_in, const int* in_sizes, int n_in,
                              void* d_out, int out_size) {
    const float* x    = (const float*)d_in[0];
    const float* cand = (const float*)d_in[1];
    const int*   ei   = (const int*)d_in[2];
    const float* cw1  = (const float*)d_in[3];
    const float* cb1  = (const float*)d_in[4];
    const float* cw2  = (const float*)d_in[5];
    const float* cb2  = (const float*)d_in[6];
    const float* m1w1 = (const float*)d_in[7];
    const float* m1b1 = (const float*)d_in[8];
    const float* m1w2 = (const float*)d_in[9];
    const float* m1b2 = (const float*)d_in[10];
    const float* m2w1 = (const float*)d_in[11];
    const float* m2b1 = (const float*)d_in[12];
    const float* m2w2 = (const float*)d_in[13];
    const float* m2b2 = (const float*)d_in[14];
    float* out = (float*)d_out;

    k_init<<<2048, 256>>>();
    k_deg<<<NE / 256, 256>>>(ei);
    k_gemm1<<<(NN + 15) / 16, 256>>>(x, cand, cw1);
    k_scatter<0><<<(int)(((long long)NE * 4) / 256), 256>>>(ei);
    k_fin1g2<<<(NN + 7) / 8, 128>>>(cb1, cw2);
    k_scatter<1><<<(int)(((long long)NE * 4) / 256), 256>>>(ei);
    k_fin2mlp1<<<(NN + 7) / 8, 128>>>(cb2, m1w1, m1b1, m1w2, m1b2, out + 131);
    k_mlp2<<<(NN + 255) / 256, 256>>>(m2w1, m2b1, m2w2, m2b2, out + 131 + NN);
    k_final<<<1, 128>>>(x, cand, out);
}